// round 12
// baseline (speedup 1.0000x reference)
#include <cuda_runtime.h>
#include <cuda_fp16.h>
#include <cstdint>

// Problem shape (fixed): B=64, T=1000, I=512, O=256
#define SNN_B 64
#define SNN_T 1000
#define SNN_I 512
#define SNN_O 256
#define ALPHA 0.95f
#define BETA  0.9f

#define CHUNKS 8
#define CHUNK_L 125              // == GEMM M-tile; 8 * 125 = 1000
#define CHAINS (SNN_B * SNN_O)   // 16384
#define MROWS (SNN_B * SNN_T)    // 64000

__device__ __half  g_h[(size_t)MROWS * SNN_O];
__device__ float2  g_end[CHAINS * CHUNKS];

__device__ __forceinline__ uint32_t smem_u32(const void* p) {
    uint32_t a;
    asm("{ .reg .u64 t; cvta.to.shared.u64 t, %1; cvt.u32.u64 %0, t; }" : "=r"(a) : "l"(p));
    return a;
}

// ===========================================================================
// Kernel 1: FP16 MMA GEMM, ping-pong double-buffered smem (1 sync/K-tile),
// fused local chunk scan in the epilogue (split across 256 threads).
//   M-tile 125 (pad 128) x N-tile 128; BK = 32 halves; 256 threads, 8 warps.
//   Stage s (s=0,1): A at sbuf + s*16KB (128 rows x 64B), B at +8KB.
//   Epilogue stage Hst (125x128 half = 31.25KB) overlaps sbuf.
// ===========================================================================
#define GBN 128
#define BKH 32
#define MTILE 125
#define STAGE_B 16384

__global__ __launch_bounds__(256, 1)
void snn_gemm_f16(const float* __restrict__ A,
                  const float* __restrict__ W,
                  __half* __restrict__ H)
{
    __shared__ __align__(16) char sbuf[2 * STAGE_B];   // 32 KB
    __shared__ float2 sPart[2][128];                   // split-scan partials

    const int tid  = threadIdx.x;
    const int lane = tid & 31;
    const int wid  = tid >> 5;
    const int wm   = wid & 3;
    const int wn   = wid >> 2;
    const int g    = lane >> 2;
    const int t4   = lane & 3;

    const int bn = blockIdx.x * GBN;         // x = N (2) -> adjacent CTAs share A
    const int bm = blockIdx.y * MTILE;       // y = M tile (512)

    // loader: row = tid>>1 (0..127), 16 floats starting at (tid&1)*16
    const int lrow = tid >> 1;
    const int lc0  = (tid & 1) * 16;
    const int arow = min(bm + lrow, MROWS - 1);   // tail-tile clamp (rows >=125 unused)
    const float* Ap = A + (size_t)arow * SNN_I + lc0;
    const float* Wp = W + (size_t)(bn + lrow) * SNN_I + lc0;

    const uint32_t sbase = smem_u32(sbuf);
    const int xrow = (lrow >> 1) & 3;
    // loader's swizzled byte offset within a stage, per 4-float group j
    // colb = (lc0 + j*4)*2 ; seg = colb>>4 ; rem = colb&15
    #define ST_OFF(j) (lrow * 64 + (((((lc0 + (j)*4) * 2) >> 4) ^ xrow) << 4) \
                                 + (((lc0 + (j)*4) * 2) & 15))

    float4 pa[4], pb[4];
    #define LOAD_REGS(kt)                                            \
    do {                                                             \
        const float* Apn = Ap + (kt) * BKH;                          \
        const float* Wpn = Wp + (kt) * BKH;                          \
        _Pragma("unroll")                                            \
        for (int j = 0; j < 4; j++) {                                \
            pa[j] = *(const float4*)(Apn + j * 4);                   \
            pb[j] = *(const float4*)(Wpn + j * 4);                   \
        }                                                            \
    } while (0)

    #define STORE_STAGE(st)                                          \
    do {                                                             \
        char* as_ = sbuf + (st) * STAGE_B;                           \
        char* bs_ = as_ + 8192;                                      \
        _Pragma("unroll")                                            \
        for (int j = 0; j < 4; j++) {                                \
            const uint32_t off = ST_OFF(j);                          \
            __half2 a0 = __floats2half2_rn(pa[j].x, pa[j].y);        \
            __half2 a1 = __floats2half2_rn(pa[j].z, pa[j].w);        \
            __half2 b0 = __floats2half2_rn(pb[j].x, pb[j].y);        \
            __half2 b1 = __floats2half2_rn(pb[j].z, pb[j].w);        \
            uint2 av = {*(uint32_t*)&a0, *(uint32_t*)&a1};           \
            uint2 bv = {*(uint32_t*)&b0, *(uint32_t*)&b1};           \
            *(uint2*)(as_ + off) = av;                               \
            *(uint2*)(bs_ + off) = bv;                               \
        }                                                            \
    } while (0)

    float c[2][8][4];
    #pragma unroll
    for (int mt = 0; mt < 2; mt++)
        #pragma unroll
        for (int nt = 0; nt < 8; nt++)
            #pragma unroll
            for (int q = 0; q < 4; q++)
                c[mt][nt][q] = 0.0f;

    LOAD_REGS(0);
    STORE_STAGE(0);
    LOAD_REGS(1);
    __syncthreads();

    #pragma unroll 1
    for (int kt = 0; kt < SNN_I / BKH; kt++) {
        const uint32_t sA = sbase + (kt & 1) * STAGE_B;
        const uint32_t sB = sA + 8192;

        #pragma unroll
        for (int s = 0; s < 2; s++) {
            uint32_t af[2][4];
            #pragma unroll
            for (int mt = 0; mt < 2; mt++) {
                const int row = wm * 32 + mt * 16 + (lane & 15);
                const int seg = s * 2 + (lane >> 4);
                const uint32_t addr = sA + row * 64 + ((seg ^ ((row >> 1) & 3)) << 4);
                asm volatile(
                    "ldmatrix.sync.aligned.m8n8.x4.shared.b16 {%0,%1,%2,%3}, [%4];"
                    : "=r"(af[mt][0]), "=r"(af[mt][1]), "=r"(af[mt][2]), "=r"(af[mt][3])
                    : "r"(addr));
            }
            uint32_t bf[4][4];
            #pragma unroll
            for (int p = 0; p < 4; p++) {
                const int row = wn * 64 + p * 16 + (lane & 15);
                const int seg = s * 2 + (lane >> 4);
                const uint32_t addr = sB + row * 64 + ((seg ^ ((row >> 1) & 3)) << 4);
                asm volatile(
                    "ldmatrix.sync.aligned.m8n8.x4.shared.b16 {%0,%1,%2,%3}, [%4];"
                    : "=r"(bf[p][0]), "=r"(bf[p][1]), "=r"(bf[p][2]), "=r"(bf[p][3])
                    : "r"(addr));
            }
            #pragma unroll
            for (int mt = 0; mt < 2; mt++)
                #pragma unroll
                for (int nt = 0; nt < 8; nt++) {
                    const int p = nt >> 1, hi = nt & 1;
                    asm volatile(
                        "mma.sync.aligned.m16n8k16.row.col.f32.f16.f16.f32 "
                        "{%0,%1,%2,%3}, {%4,%5,%6,%7}, {%8,%9}, {%0,%1,%2,%3};"
                        : "+f"(c[mt][nt][0]), "+f"(c[mt][nt][1]),
                          "+f"(c[mt][nt][2]), "+f"(c[mt][nt][3])
                        : "r"(af[mt][0]), "r"(af[mt][1]), "r"(af[mt][2]), "r"(af[mt][3]),
                          "r"(bf[p][hi]), "r"(bf[p][hi + 2]));
                }
        }

        if (kt + 1 < SNN_I / BKH) {
            STORE_STAGE((kt + 1) & 1);   // idle stage: no race with current reads
            __syncthreads();
            if (kt + 2 < SNN_I / BKH) LOAD_REGS(kt + 2);
        }
    }
    __syncthreads();   // all MMA reads of sbuf done before Hst overwrite

    // ---- Epilogue: global H stores + smem transpose stage ----
    __half* Hst = (__half*)sbuf;   // 125 x 128, overlaps ping-pong buffers
    #pragma unroll
    for (int mt = 0; mt < 2; mt++) {
        #pragma unroll
        for (int nt = 0; nt < 8; nt++) {
            const int lr0  = wm * 32 + mt * 16 + g;     // <= 119
            const int lcol = wn * 64 + nt * 8 + t4 * 2;
            __half2 v0 = __floats2half2_rn(c[mt][nt][0], c[mt][nt][1]);
            __half2 v1 = __floats2half2_rn(c[mt][nt][2], c[mt][nt][3]);
            *(__half2*)(H + (size_t)(bm + lr0) * SNN_O + bn + lcol) = v0;
            *(__half2*)(&Hst[lr0 * 128 + lcol]) = v0;
            const int lr1 = lr0 + 8;
            if (lr1 < MTILE) {
                *(__half2*)(H + (size_t)(bm + lr1) * SNN_O + bn + lcol) = v1;
                *(__half2*)(&Hst[lr1 * 128 + lcol]) = v1;
            }
        }
    }
    __syncthreads();

    // ---- Fused phase-1: split local scan (rows 0..61 | 62..124), combine ----
    {
        const int hf  = tid >> 7;          // 0: 62 steps, 1: 63 steps
        const int col = tid & 127;
        const int t0  = hf ? 62 : 0;
        const int cnt = hf ? 63 : 62;
        const __half* cp = Hst + t0 * 128 + col;

        float f = 0.0f, o = 0.0f;
        int t = 0;
        #pragma unroll 1
        for (; t + 7 <= cnt; t += 7) {
            float v[7];
            #pragma unroll
            for (int j = 0; j < 7; j++)
                v[j] = __half2float(cp[(t + j) * 128]);
            #pragma unroll
            for (int j = 0; j < 7; j++) {
                float nf = fmaf(ALPHA, f, v[j]);
                o = fmaf(BETA, o, f);
                f = nf;
            }
        }
        #pragma unroll 1
        for (; t < cnt; t++) {
            float v = __half2float(cp[t * 128]);
            float nf = fmaf(ALPHA, f, v);
            o = fmaf(BETA, o, f);
            f = nf;
        }
        sPart[hf][col] = make_float2(f, o);
    }
    __syncthreads();
    if (tid < 128) {
        float2 sA2 = sPart[0][tid];
        float2 sB2 = sPart[1][tid];
        // chunk end = M^63 * sA + sB,  M^63 = [[a63,0],[c63,b63]]
        const float a63 = exp2f(63.0f * log2f(ALPHA));
        const float b63 = exp2f(63.0f * log2f(BETA));
        const float c63 = (a63 - b63) / (ALPHA - BETA);
        float f = fmaf(a63, sA2.x, sB2.x);
        float o = fmaf(b63, sA2.y, fmaf(c63, sA2.x, sB2.y));
        const int b    = blockIdx.y >> 3;
        const int cidx = blockIdx.y & 7;
        g_end[((b * CHUNKS + cidx) << 8) | (bn + tid)] = make_float2(f, o);
    }
    #undef ST_OFF
    #undef LOAD_REGS
    #undef STORE_STAGE
}

// ===========================================================================
// Kernel 2: fused combine + rescan. 2 chains/thread, 128-thread blocks.
// ===========================================================================
__global__ __launch_bounds__(128)
void snn_scan_phase3(const __half* __restrict__ H, float* __restrict__ out)
{
    const int idx  = blockIdx.x * blockDim.x + threadIdx.x;  // 0..65535
    const int o2   = idx & 127;
    const int rest = idx >> 7;
    const int cidx = rest & 7;
    const int b    = rest >> 3;

    const float aL = exp2f((float)CHUNK_L * log2f(ALPHA));
    const float bL = exp2f((float)CHUNK_L * log2f(BETA));
    const float cL = (aL - bL) / (ALPHA - BETA);

    float f0 = 0.f, o0 = 0.f, f1 = 0.f, o1 = 0.f;
    for (int c2 = 0; c2 < cidx; c2++) {
        const float4 e = *(const float4*)&g_end[((b * CHUNKS + c2) << 8) | (o2 * 2)];
        float nf0 = fmaf(aL, f0, e.x);
        float no0 = fmaf(bL, o0, fmaf(cL, f0, e.y));
        float nf1 = fmaf(aL, f1, e.z);
        float no1 = fmaf(bL, o1, fmaf(cL, f1, e.w));
        f0 = nf0; o0 = no0; f1 = nf1; o1 = no1;
    }

    const size_t ebase = ((size_t)b * SNN_T + cidx * CHUNK_L) * SNN_O + o2 * 2;
    const __half* hp = H + ebase;
    float*        op = out + ebase;

    #pragma unroll 1
    for (int t = 0; t < CHUNK_L; t += 5) {
        __half2 v[5];
        #pragma unroll
        for (int j = 0; j < 5; j++)
            v[j] = *(const __half2*)(hp + (size_t)(t + j) * SNN_O);
        #pragma unroll
        for (int j = 0; j < 5; j++) {
            float h0 = __low2float(v[j]), h1 = __high2float(v[j]);
            float n0 = fmaf(ALPHA, f0, h0);
            float n1 = fmaf(ALPHA, f1, h1);
            o0 = fmaf(BETA, o0, f0);
            o1 = fmaf(BETA, o1, f1);
            f0 = n0; f1 = n1;
            float2 w = {o0, o1};
            *(float2*)(op + (size_t)(t + j) * SNN_O) = w;
        }
    }
}

// ---------------------------------------------------------------------------
extern "C" void kernel_launch(void* const* d_in, const int* in_sizes, int n_in,
                              void* d_out, int out_size)
{
    const float* inputs = (const float*)d_in[0];   // (B, T, I)
    const float* W      = (const float*)d_in[1];   // (O, I)
    float* out = (float*)d_out;                    // (B, T, O) fp32

    __half* h;
    cudaGetSymbolAddress((void**)&h, g_h);

    dim3 gemm_grid(SNN_O / GBN, MROWS / MTILE);    // (2, 512): N fastest
    snn_gemm_f16<<<gemm_grid, 256>>>(inputs, W, h);

    const int p3threads = CHAINS * CHUNKS / 2;     // 65536
    snn_scan_phase3<<<p3threads / 128, 128>>>(h, out);
}